// round 13
// baseline (speedup 1.0000x reference)
#include <cuda_runtime.h>
#include <cuda_fp16.h>
#include <cstdint>
#include <cstddef>

// ============================================================================
// HolographicMemory on GB300 (base-sm_103):
//   G1: energy = x * [kr|ki]^T via fp16 HMMA (x converted in-kernel from fp32),
//       softmax, d' = 512*attn - 1, per-row int8 quantization -> g_dq, g_s
//   G2: out = vbar + (d' * V)/512 via INT8 IMMA m16n8k32 (V per-column int8)
// ============================================================================

#define TEMPERATURE 0.04419417382415922f   // 1/sqrt(512)

// ---------------- device scratch -------------------------------------------
__device__ __half       g_Kh[512 * 1024];                 // [mem, 2*head] fp16
__device__ signed char  g_Vq[1024 * 512];                 // VT quantized: [h, mem]
__device__ float        g_Th[1024];                       // V col scale: max/127
__device__ float        g_vbar[1024];                     // colmean(V)
__device__ signed char  g_dq[(size_t)32768 * 512];        // d' quantized
__device__ float        g_s[32768];                       // row scale: mx/(127*512)

// ---------------- helpers ---------------------------------------------------
__device__ __forceinline__ uint32_t smem_u32(const void* p) {
    uint32_t a;
    asm("{ .reg .u64 t; cvta.to.shared.u64 t, %1; cvt.u32.u64 %0, t; }" : "=r"(a) : "l"(p));
    return a;
}
__device__ __forceinline__ uint32_t SWZ(uint32_t x) { return x ^ ((x >> 3) & 0x70); }

#define CP_ASYNC16(dst_u32, src_ptr) \
    asm volatile("cp.async.cg.shared.global [%0], [%1], 16;" :: "r"(dst_u32), "l"(src_ptr) : "memory")
#define CP_COMMIT() asm volatile("cp.async.commit_group;" ::: "memory")
#define CP_WAIT0()  asm volatile("cp.async.wait_group 0;" ::: "memory")

#define LDSM_X4(R, addr) \
    asm volatile("ldmatrix.sync.aligned.m8n8.x4.shared.b16 {%0,%1,%2,%3}, [%4];" \
        : "=r"((R)[0]), "=r"((R)[1]), "=r"((R)[2]), "=r"((R)[3]) : "r"(addr))

__device__ __forceinline__ void mma16816h(uint32_t* c, const uint32_t* a, uint32_t b0, uint32_t b1) {
    asm volatile(
        "mma.sync.aligned.m16n8k16.row.col.f16.f16.f16.f16 "
        "{%0,%1}, {%2,%3,%4,%5}, {%6,%7}, {%0,%1};"
        : "+r"(c[0]), "+r"(c[1])
        : "r"(a[0]), "r"(a[1]), "r"(a[2]), "r"(a[3]), "r"(b0), "r"(b1));
}
__device__ __forceinline__ void mma16832s8(int* c, const uint32_t* a, uint32_t b0, uint32_t b1) {
    asm volatile(
        "mma.sync.aligned.m16n8k32.row.col.s32.s8.s8.s32 "
        "{%0,%1,%2,%3}, {%4,%5,%6,%7}, {%8,%9}, {%0,%1,%2,%3};"
        : "+r"(c[0]), "+r"(c[1]), "+r"(c[2]), "+r"(c[3])
        : "r"(a[0]), "r"(a[1]), "r"(a[2]), "r"(a[3]), "r"(b0), "r"(b1));
}

// ============================================================================
// prep kernel: grid 1536 x 256
//   b in [0,1024): V column h -> g_Vq row, g_Th, g_vbar
//   b in [1024,1536): Kh row m
// ============================================================================
__global__ void prep_kernel(const float* __restrict__ kr, const float* __restrict__ ki,
                            const float* __restrict__ vr, const float* __restrict__ vi) {
    int b = blockIdx.x, t = threadIdx.x;
    if (b < 1024) {
        __shared__ float stash[512];
        __shared__ float redS[8], redM[8];
        int h = b;
        const float* src = (h < 512) ? (vr + h) : (vi + (h - 512));
        float sum = 0.0f, mx = 0.0f;
        for (int m = t; m < 512; m += 256) {
            float v = src[(size_t)m * 512];
            stash[m] = v;
            sum += v;
            mx = fmaxf(mx, fabsf(v));
        }
        #pragma unroll
        for (int o = 16; o; o >>= 1) {
            sum += __shfl_xor_sync(0xffffffffu, sum, o);
            mx = fmaxf(mx, __shfl_xor_sync(0xffffffffu, mx, o));
        }
        if ((t & 31) == 0) { redS[t >> 5] = sum; redM[t >> 5] = mx; }
        __syncthreads();
        float ts = 0.0f, tm = 0.0f;
        #pragma unroll
        for (int i = 0; i < 8; i++) { ts += redS[i]; tm = fmaxf(tm, redM[i]); }
        if (t == 0) {
            g_vbar[h] = ts * (1.0f / 512.0f);
            g_Th[h]   = tm * (1.0f / 127.0f) + 1e-30f;
        }
        float inv = 127.0f / fmaxf(tm, 1e-30f);
        for (int m = t; m < 512; m += 256) {
            int q = __float2int_rn(stash[m] * inv);
            q = max(-127, min(127, q));
            g_Vq[(size_t)h * 512 + m] = (signed char)q;
        }
    } else {
        int m = b - 1024;
        for (int c = t; c < 1024; c += 256) {
            float v = (c < 512) ? kr[(size_t)m * 512 + c] : ki[(size_t)m * 512 + c - 512];
            g_Kh[(size_t)m * 1024 + c] = __float2half(v);
        }
    }
}

// ============================================================================
// GEMM1: energy[128 x 512] tile = x[128 x 1024] * Kh^T; fp16 HMMA, f16 acc.
//   A: LDG fp32 -> cvt -> STS (register prefetch).  B: cp.async.
//   512 threads = 16 warps (4M x 4N), warp tile 32 x 128, 2-stage.
//   Epilogue: softmax, per-row int8 quantize of d' = 512*attn - 1.
// ============================================================================
static constexpr int G1_A_STAGE = 16384;   // 128 x 64 fp16 (128B rows)
static constexpr int G1_B_STAGE = 65536;   // 512 x 64 fp16
static constexpr int G1_B_BASE  = 2 * G1_A_STAGE;
static constexpr int G1_SMEM    = 2 * (G1_A_STAGE + G1_B_STAGE);  // 163840

__global__ void __launch_bounds__(512, 1) gemm1_kernel(const float* __restrict__ x) {
    extern __shared__ char S[];
    const uint32_t sb = smem_u32(S);

    const int tid = threadIdx.x, lid = tid & 31, w = tid >> 5;
    const int wm = w >> 2, wn = w & 3;
    const int bm0 = blockIdx.x * 128;

    // ---- A prefetch (fp32 regs) + convert/store ----
    float4 xv[4];
    const int arow = tid >> 4, afo = tid & 15;   // row 0..31 per it-step of 32? no:
    // per thread: 4 elements u = tid + i*512 -> row=u>>4 (0..127), fo=u&15
    auto ldgA = [&](int c) {
        const int kc = c * 64;
        #pragma unroll
        for (int i = 0; i < 4; i++) {
            int u = tid + i * 512, row = u >> 4, fo = u & 15;
            xv[i] = *(const float4*)(x + (size_t)(bm0 + row) * 1024 + kc + fo * 4);
        }
    };
    auto stsA = [&](int st) {
        char* ab = S + st * G1_A_STAGE;
        #pragma unroll
        for (int i = 0; i < 4; i++) {
            int u = tid + i * 512, row = u >> 4, fo = u & 15;
            __half2 p0 = __float22half2_rn(make_float2(xv[i].x, xv[i].y));
            __half2 p1 = __float22half2_rn(make_float2(xv[i].z, xv[i].w));
            uint2 q = make_uint2(*(uint32_t*)&p0, *(uint32_t*)&p1);
            *(uint2*)(ab + SWZ((uint32_t)(row * 128 + fo * 8))) = q;
        }
    };
    auto loadB = [&](int c, int st) {
        const int kc = c * 64;
        const uint32_t bb = sb + G1_B_BASE + st * G1_B_STAGE;
        #pragma unroll
        for (int it = 0; it < 8; it++) {
            int u = tid + it * 512, row = u >> 3, seg = u & 7;
            const char* src = (const char*)(g_Kh + (size_t)row * 1024 + kc + seg * 8);
            CP_ASYNC16(bb + SWZ((uint32_t)(row * 128 + seg * 16)), src);
        }
        CP_COMMIT();
    };
    (void)arow; (void)afo;

    uint32_t aoff[2], boff[8];
    #pragma unroll
    for (int mi = 0; mi < 2; mi++)
        aoff[mi] = (uint32_t)((wm * 32 + mi * 16 + (lid & 15)) * 128 + (lid >> 4) * 16);
    #pragma unroll
    for (int g = 0; g < 8; g++)
        boff[g] = (uint32_t)((wn * 128 + g * 16 + (lid & 15)) * 128 + (lid >> 4) * 16);

    uint32_t hacc[2][16][2];
    #pragma unroll
    for (int mi = 0; mi < 2; mi++)
        #pragma unroll
        for (int nf = 0; nf < 16; nf++)
            hacc[mi][nf][0] = hacc[mi][nf][1] = 0u;

    auto compute = [&](int st) {
        const uint32_t ab = sb + st * G1_A_STAGE;
        const uint32_t bb = sb + G1_B_BASE + st * G1_B_STAGE;
        #pragma unroll
        for (int ks = 0; ks < 4; ks++) {
            uint32_t a[2][4];
            #pragma unroll
            for (int mi = 0; mi < 2; mi++) LDSM_X4(a[mi], ab + SWZ(aoff[mi] + ks * 32));
            #pragma unroll
            for (int g = 0; g < 8; g++) {
                uint32_t bf[4];
                LDSM_X4(bf, bb + SWZ(boff[g] + ks * 32));
                #pragma unroll
                for (int mi = 0; mi < 2; mi++) {
                    mma16816h(hacc[mi][2 * g],     a[mi], bf[0], bf[2]);
                    mma16816h(hacc[mi][2 * g + 1], a[mi], bf[1], bf[3]);
                }
            }
        }
    };

    // ---- mainloop (16 chunks of K=64) ----
    ldgA(0);
    loadB(0, 0);
    #pragma unroll 1
    for (int c = 0; c < 16; c++) {
        stsA(c & 1);
        if (c < 15) ldgA(c + 1);
        CP_WAIT0();
        __syncthreads();
        if (c < 15) loadB(c + 1, (c + 1) & 1);
        compute(c & 1);
    }
    __syncthreads();

    // ---- expand to fp32, exponentiate ----
    float acc[2][16][4];
    #pragma unroll
    for (int mi = 0; mi < 2; mi++)
        #pragma unroll
        for (int nf = 0; nf < 16; nf++) {
            float2 lo = __half22float2(*(__half2*)&hacc[mi][nf][0]);
            float2 hi = __half22float2(*(__half2*)&hacc[mi][nf][1]);
            acc[mi][nf][0] = __expf(lo.x * TEMPERATURE);
            acc[mi][nf][1] = __expf(lo.y * TEMPERATURE);
            acc[mi][nf][2] = __expf(hi.x * TEMPERATURE);
            acc[mi][nf][3] = __expf(hi.y * TEMPERATURE);
        }

    // ---- reductions: sum / max / min per row ----
    float* redS = (float*)S;            // 128 x 4
    float* redX = (float*)S + 512;      // max
    float* redN = (float*)S + 1024;     // min
    #pragma unroll
    for (int mi = 0; mi < 2; mi++) {
        float sA = 0.f, sB = 0.f, xA = 0.f, xB = 0.f, nA = 1e30f, nB = 1e30f;
        #pragma unroll
        for (int nf = 0; nf < 16; nf++) {
            float e0 = acc[mi][nf][0], e1 = acc[mi][nf][1];
            float e2 = acc[mi][nf][2], e3 = acc[mi][nf][3];
            sA += e0 + e1;  sB += e2 + e3;
            xA = fmaxf(xA, fmaxf(e0, e1));  xB = fmaxf(xB, fmaxf(e2, e3));
            nA = fminf(nA, fminf(e0, e1));  nB = fminf(nB, fminf(e2, e3));
        }
        #pragma unroll
        for (int o = 1; o <= 2; o <<= 1) {
            sA += __shfl_xor_sync(0xffffffffu, sA, o);
            sB += __shfl_xor_sync(0xffffffffu, sB, o);
            xA = fmaxf(xA, __shfl_xor_sync(0xffffffffu, xA, o));
            xB = fmaxf(xB, __shfl_xor_sync(0xffffffffu, xB, o));
            nA = fminf(nA, __shfl_xor_sync(0xffffffffu, nA, o));
            nB = fminf(nB, __shfl_xor_sync(0xffffffffu, nB, o));
        }
        if ((lid & 3) == 0) {
            int r = wm * 32 + mi * 16 + (lid >> 2);
            redS[r * 4 + wn] = sA;       redS[(r + 8) * 4 + wn] = sB;
            redX[r * 4 + wn] = xA;       redX[(r + 8) * 4 + wn] = xB;
            redN[r * 4 + wn] = nA;       redN[(r + 8) * 4 + wn] = nB;
        }
    }
    __syncthreads();

    // ---- quantize d' = e*sc - 1 to int8, write g_dq / g_s ----
    #pragma unroll
    for (int mi = 0; mi < 2; mi++) {
        int rA = wm * 32 + mi * 16 + (lid >> 2), rB = rA + 8;
        float sumA = redS[rA*4] + redS[rA*4+1] + redS[rA*4+2] + redS[rA*4+3];
        float sumB = redS[rB*4] + redS[rB*4+1] + redS[rB*4+2] + redS[rB*4+3];
        float xA = fmaxf(fmaxf(redX[rA*4], redX[rA*4+1]), fmaxf(redX[rA*4+2], redX[rA*4+3]));
        float xB = fmaxf(fmaxf(redX[rB*4], redX[rB*4+1]), fmaxf(redX[rB*4+2], redX[rB*4+3]));
        float nA = fminf(fminf(redN[rA*4], redN[rA*4+1]), fminf(redN[rA*4+2], redN[rA*4+3]));
        float nB = fminf(fminf(redN[rB*4], redN[rB*4+1]), fminf(redN[rB*4+2], redN[rB*4+3]));
        float scA = 512.0f / sumA, scB = 512.0f / sumB;
        float mxA = fmaxf(fmaxf(xA * scA - 1.0f, 1.0f - nA * scA), 1e-12f);
        float mxB = fmaxf(fmaxf(xB * scB - 1.0f, 1.0f - nB * scB), 1e-12f);
        float invA = 127.0f / mxA, invB = 127.0f / mxB;
        if (wn == 0 && (lid & 3) == 0) {
            g_s[bm0 + rA] = mxA * (1.0f / (127.0f * 512.0f));
            g_s[bm0 + rB] = mxB * (1.0f / (127.0f * 512.0f));
        }
        size_t baseA = (size_t)(bm0 + rA) * 512, baseB = (size_t)(bm0 + rB) * 512;
        #pragma unroll
        for (int nf = 0; nf < 16; nf++) {
            int gc = wn * 128 + nf * 8 + 2 * (lid & 3);
            int q0 = __float2int_rn((acc[mi][nf][0] * scA - 1.0f) * invA);
            int q1 = __float2int_rn((acc[mi][nf][1] * scA - 1.0f) * invA);
            int q2 = __float2int_rn((acc[mi][nf][2] * scB - 1.0f) * invB);
            int q3 = __float2int_rn((acc[mi][nf][3] * scB - 1.0f) * invB);
            q0 = max(-127, min(127, q0)); q1 = max(-127, min(127, q1));
            q2 = max(-127, min(127, q2)); q3 = max(-127, min(127, q3));
            *(short*)(g_dq + baseA + gc) = (short)((q0 & 0xFF) | ((q1 & 0xFF) << 8));
            *(short*)(g_dq + baseB + gc) = (short)((q2 & 0xFF) | ((q3 & 0xFF) << 8));
        }
    }
}

// ============================================================================
// GEMM2: out[64 x 512 half] = vbar + (dq * Vq) * S_n * T_h ; INT8 m16n8k32.
//   256 threads = 8 warps (2M x 4N), warp tile 32 x 128, 2-stage.
//   smem rows padded to 128B (64B of s8 data per row).
// ============================================================================
static constexpr int G2_A_STAGE = 8192;    // 64 rows x 128B
static constexpr int G2_B_STAGE = 65536;   // 512 rows x 128B
static constexpr int G2_B_BASE  = 2 * G2_A_STAGE;
static constexpr int G2_SMEM    = 2 * (G2_A_STAGE + G2_B_STAGE);  // 147456

__global__ void __launch_bounds__(256, 1) gemm2_kernel(float* __restrict__ outp) {
    extern __shared__ char S[];
    const uint32_t sb = smem_u32(S);

    const int tid = threadIdx.x, lid = tid & 31, w = tid >> 5;
    const int wm = w >> 2, wn = w & 3;            // 2(M) x 4(N)
    const int bm0 = blockIdx.x * 64;
    const int hbase = blockIdx.y * 512;

    auto load_chunk = [&](int c, int st) {
        const int kc = c * 64;
        const uint32_t ab = sb + st * G2_A_STAGE;
        const uint32_t bb = sb + G2_B_BASE + st * G2_B_STAGE;
        {   // A: 64 rows x 4 segs = 256 ops
            int row = tid >> 2, seg = tid & 3;
            const char* src = (const char*)(g_dq + (size_t)(bm0 + row) * 512 + kc + seg * 16);
            CP_ASYNC16(ab + SWZ((uint32_t)(row * 128 + seg * 16)), src);
        }
        #pragma unroll
        for (int it = 0; it < 8; it++) {              // B: 512 rows x 4 segs
            int u = tid + it * 256, row = u >> 2, seg = u & 3;
            const char* src = (const char*)(g_Vq + (size_t)(hbase + row) * 512 + kc + seg * 16);
            CP_ASYNC16(bb + SWZ((uint32_t)(row * 128 + seg * 16)), src);
        }
        CP_COMMIT();
    };

    uint32_t aoff[2], boff[8];
    #pragma unroll
    for (int mi = 0; mi < 2; mi++)
        aoff[mi] = (uint32_t)((wm * 32 + mi * 16 + (lid & 15)) * 128 + (lid >> 4) * 16);
    #pragma unroll
    for (int g = 0; g < 8; g++)
        boff[g] = (uint32_t)((wn * 128 + g * 16 + (lid & 15)) * 128 + (lid >> 4) * 16);

    int acc[2][16][4];
    #pragma unroll
    for (int mi = 0; mi < 2; mi++)
        #pragma unroll
        for (int nf = 0; nf < 16; nf++)
            #pragma unroll
            for (int j = 0; j < 4; j++) acc[mi][nf][j] = 0;

    auto compute = [&](int st) {
        const uint32_t ab = sb + st * G2_A_STAGE;
        const uint32_t bb = sb + G2_B_BASE + st * G2_B_STAGE;
        #pragma unroll
        for (int ks = 0; ks < 2; ks++) {              // k64 chunk = 2 x k32
            uint32_t a[2][4];
            #pragma unroll
            for (int mi = 0; mi < 2; mi++) LDSM_X4(a[mi], ab + SWZ(aoff[mi] + ks * 32));
            #pragma unroll
            for (int g = 0; g < 8; g++) {
                uint32_t bf[4];
                LDSM_X4(bf, bb + SWZ(boff[g] + ks * 32));
                #pragma unroll
                for (int mi = 0; mi < 2; mi++) {
                    mma16832s8(acc[mi][2 * g],     a[mi], bf[0], bf[2]);
                    mma16832s8(acc[mi][2 * g + 1], a[mi], bf[1], bf[3]);
                }
            }
        }
    };

    load_chunk(0, 0);
    #pragma unroll 1
    for (int c = 0; c < 8; c++) {                     // K=512 -> 8 chunks
        CP_WAIT0();
        __syncthreads();
        if (c + 1 < 8) load_chunk(c + 1, (c + 1) & 1);
        compute(c & 1);
    }

    // ---- epilogue: out = vbar + acc * S_row * T_col ----
    #pragma unroll
    for (int mi = 0; mi < 2; mi++) {
        int rA = wm * 32 + mi * 16 + (lid >> 2), rB = rA + 8;
        float sA = g_s[bm0 + rA], sB = g_s[bm0 + rB];
        size_t rowA = (size_t)(bm0 + rA) * 1024 + hbase;
        size_t rowB = (size_t)(bm0 + rB) * 1024 + hbase;
        #pragma unroll
        for (int nf = 0; nf < 16; nf++) {
            int gc = wn * 128 + nf * 8 + 2 * (lid & 3);
            float2 vb = *(const float2*)(g_vbar + hbase + gc);
            float2 th = *(const float2*)(g_Th + hbase + gc);
            float2 o0 = make_float2(fmaf((float)acc[mi][nf][0] * sA, th.x, vb.x),
                                    fmaf((float)acc[mi][nf][1] * sA, th.y, vb.y));
            float2 o1 = make_float2(fmaf((float)acc[mi][nf][2] * sB, th.x, vb.x),
                                    fmaf((float)acc[mi][nf][3] * sB, th.y, vb.y));
            *(float2*)(outp + rowA + gc) = o0;
            *(float2*)(outp + rowB + gc) = o1;
        }
    }
}

// ============================================================================
extern "C" void kernel_launch(void* const* d_in, const int* in_sizes, int n_in,
                              void* d_out, int out_size) {
    (void)in_sizes; (void)n_in; (void)out_size;
    const float* x  = (const float*)d_in[0];
    const float* kr = (const float*)d_in[1];
    const float* ki = (const float*)d_in[2];
    const float* vr = (const float*)d_in[3];
    const float* vi = (const float*)d_in[4];
    float* out = (float*)d_out;

    cudaFuncSetAttribute(gemm1_kernel, cudaFuncAttributeMaxDynamicSharedMemorySize, G1_SMEM);
    cudaFuncSetAttribute(gemm2_kernel, cudaFuncAttributeMaxDynamicSharedMemorySize, G2_SMEM);

    prep_kernel<<<1536, 256>>>(kr, ki, vr, vi);
    gemm1_kernel<<<256, 512, G1_SMEM>>>(x);
    gemm2_kernel<<<dim3(512, 2), 256, G2_SMEM>>>(out);
}

// round 16
// speedup vs baseline: 1.5965x; 1.5965x over previous
#include <cuda_runtime.h>
#include <cuda_fp16.h>
#include <cstdint>
#include <cstddef>

// ============================================================================
// HolographicMemory on GB300 (base-sm_103 path): fp16 HMMA (f16 accum) +
// ldmatrix + cp.async. Round-11 structure; x->fp16 conversion fused into G1
// via fp32 smem staging (no register pressure).
//
//   prep : g_Kh[512x1024] = fp16([kr|ki]); g_VT[1024x512] = fp16(V^T);
//          g_vbar[1024] = colmean(V) fp32
//   G1   : energy = x * Kh^T (f16 acc); softmax; g_d = 512*attn - 1 (fp16)
//   G2   : out = vbar + (g_d * V) / 512   (B = VT, f16 acc)
// ============================================================================

#define TEMPERATURE 0.04419417382415922f   // 1/sqrt(512)

// ---------------- device scratch (no allocation allowed) --------------------
__device__ __half g_Kh[512 * 1024];
__device__ __half g_VT[1024 * 512];
__device__ float  g_vbar[1024];
__device__ __half g_d[(size_t)32768 * 512];

// ---------------- helpers ---------------------------------------------------
__device__ __forceinline__ uint32_t smem_u32(const void* p) {
    uint32_t a;
    asm("{ .reg .u64 t; cvta.to.shared.u64 t, %1; cvt.u32.u64 %0, t; }" : "=r"(a) : "l"(p));
    return a;
}
__device__ __forceinline__ uint32_t SWZ(uint32_t x) { return x ^ ((x >> 3) & 0x70); }

#define CP_ASYNC16(dst_u32, src_ptr) \
    asm volatile("cp.async.cg.shared.global [%0], [%1], 16;" :: "r"(dst_u32), "l"(src_ptr) : "memory")
#define CP_COMMIT() asm volatile("cp.async.commit_group;" ::: "memory")
#define CP_WAIT0()  asm volatile("cp.async.wait_group 0;" ::: "memory")

#define LDSM_X4(R, addr) \
    asm volatile("ldmatrix.sync.aligned.m8n8.x4.shared.b16 {%0,%1,%2,%3}, [%4];" \
        : "=r"((R)[0]), "=r"((R)[1]), "=r"((R)[2]), "=r"((R)[3]) : "r"(addr))

__device__ __forceinline__ void mma16816h(uint32_t* c, const uint32_t* a, uint32_t b0, uint32_t b1) {
    asm volatile(
        "mma.sync.aligned.m16n8k16.row.col.f16.f16.f16.f16 "
        "{%0,%1}, {%2,%3,%4,%5}, {%6,%7}, {%0,%1};"
        : "+r"(c[0]), "+r"(c[1])
        : "r"(a[0]), "r"(a[1]), "r"(a[2]), "r"(a[3]), "r"(b0), "r"(b1));
}

// ---------------- G1 smem layout --------------------------------------------
// A32 stage x2 (128 rows x 64 fp32 = 32KB), A16 single (16KB), B stage x2 (64KB)
static constexpr int G1_A32_STAGE = 32768;
static constexpr int G1_A16_OFF   = 65536;
static constexpr int G1_B_OFF     = 81920;
static constexpr int G1_B_STAGE   = 65536;
static constexpr int G1_SMEM      = 212992;

// ---------------- G2 smem layout (round-11) ---------------------------------
static constexpr int G2_A_STAGE = 16384;   // 128 x 64 fp16
static constexpr int G2_B_STAGE = 65536;   // 512 x 64 fp16
static constexpr int G2_B_BASE  = 2 * G2_A_STAGE;
static constexpr int G2_SMEM    = 2 * (G2_A_STAGE + G2_B_STAGE);  // 163840

// ============================================================================
// prep kernel: grid 1536 x 256 (keys/values only; tiny)
// ============================================================================
__global__ void prep_kernel(const float* __restrict__ kr, const float* __restrict__ ki,
                            const float* __restrict__ vr, const float* __restrict__ vi) {
    int b = blockIdx.x, t = threadIdx.x;
    if (b < 1024) {
        int h = b;
        const float* src = (h < 512) ? (vr + h) : (vi + (h - 512));
        float sum = 0.0f;
        for (int m = t; m < 512; m += 256) {
            float v = src[(size_t)m * 512];
            g_VT[(size_t)h * 512 + m] = __float2half(v);
            sum += v;
        }
        __shared__ float red[8];
        #pragma unroll
        for (int o = 16; o; o >>= 1) sum += __shfl_xor_sync(0xffffffffu, sum, o);
        if ((t & 31) == 0) red[t >> 5] = sum;
        __syncthreads();
        if (t == 0) {
            float s = 0.0f;
            #pragma unroll
            for (int i = 0; i < 8; i++) s += red[i];
            g_vbar[h] = s * (1.0f / 512.0f);
        }
    } else {
        int m = b - 1024;
        for (int c = t; c < 1024; c += 256) {
            float v = (c < 512) ? kr[(size_t)m * 512 + c] : ki[(size_t)m * 512 + c - 512];
            g_Kh[(size_t)m * 1024 + c] = __float2half(v);
        }
    }
}

// ============================================================================
// GEMM1: energy[128 x 512] = x[128 x 1024] * Kh^T; K chunks of 64.
//   A: cp.async fp32 -> smem stage -> convert -> fp16 A16 (single buffer).
//   512 threads = 16 warps (4M x 4N), warp tile 32 x 128, f16 accumulators.
//   Epilogue: softmax; g_d = 512*attn - 1 (fp16).
// ============================================================================
__global__ void __launch_bounds__(512, 1) gemm1_kernel(const float* __restrict__ x) {
    extern __shared__ char S[];
    const uint32_t sb = smem_u32(S);

    const int tid = threadIdx.x, lid = tid & 31, w = tid >> 5;
    const int wm = w >> 2, wn = w & 3;
    const int bm0 = blockIdx.x * 128;

    auto load_chunk = [&](int c, int st) {
        const int kc = c * 64;
        const uint32_t a32 = sb + st * G1_A32_STAGE;
        const uint32_t bb  = sb + G1_B_OFF + st * G1_B_STAGE;
        #pragma unroll
        for (int it = 0; it < 4; it++) {                 // A fp32: 128 rows x 16 segs
            int u = tid + it * 512, row = u >> 4, seg = u & 15;
            const char* src = (const char*)(x + (size_t)(bm0 + row) * 1024 + kc + seg * 4);
            CP_ASYNC16(a32 + (uint32_t)(row * 256 + seg * 16), src);
        }
        #pragma unroll
        for (int it = 0; it < 8; it++) {                 // B fp16: 512 rows x 8 segs
            int u = tid + it * 512, row = u >> 3, seg = u & 7;
            const char* src = (const char*)(g_Kh + (size_t)row * 1024 + kc + seg * 8);
            CP_ASYNC16(bb + SWZ((uint32_t)(row * 128 + seg * 16)), src);
        }
        CP_COMMIT();
    };

    auto convertA = [&](int st) {
        const float4* a32 = (const float4*)(S + st * G1_A32_STAGE);
        char* a16 = S + G1_A16_OFF;
        #pragma unroll
        for (int i = 0; i < 4; i++) {
            int u = tid + i * 512;                        // 2048 float4 total
            float4 v = a32[u];
            int row = u >> 4, fo = u & 15;                // fo: 4-float (8B fp16) unit
            __half2 p0 = __float22half2_rn(make_float2(v.x, v.y));
            __half2 p1 = __float22half2_rn(make_float2(v.z, v.w));
            uint2 q = make_uint2(*(uint32_t*)&p0, *(uint32_t*)&p1);
            *(uint2*)(a16 + SWZ((uint32_t)(row * 128 + fo * 8))) = q;
        }
    };

    uint32_t aoff[2], boff[8];
    #pragma unroll
    for (int mi = 0; mi < 2; mi++)
        aoff[mi] = (uint32_t)((wm * 32 + mi * 16 + (lid & 15)) * 128 + (lid >> 4) * 16);
    #pragma unroll
    for (int g = 0; g < 8; g++)
        boff[g] = (uint32_t)((wn * 128 + g * 16 + (lid & 15)) * 128 + (lid >> 4) * 16);

    uint32_t hacc[2][16][2];
    #pragma unroll
    for (int mi = 0; mi < 2; mi++)
        #pragma unroll
        for (int nf = 0; nf < 16; nf++)
            hacc[mi][nf][0] = hacc[mi][nf][1] = 0u;

    auto compute = [&](int st) {
        const uint32_t ab = sb + G1_A16_OFF;
        const uint32_t bb = sb + G1_B_OFF + st * G1_B_STAGE;
        #pragma unroll
        for (int ks = 0; ks < 4; ks++) {
            uint32_t a[2][4];
            #pragma unroll
            for (int mi = 0; mi < 2; mi++) LDSM_X4(a[mi], ab + SWZ(aoff[mi] + ks * 32));
            #pragma unroll
            for (int g = 0; g < 8; g++) {
                uint32_t bf[4];
                LDSM_X4(bf, bb + SWZ(boff[g] + ks * 32));
                #pragma unroll
                for (int mi = 0; mi < 2; mi++) {
                    mma16816h(hacc[mi][2 * g],     a[mi], bf[0], bf[2]);
                    mma16816h(hacc[mi][2 * g + 1], a[mi], bf[1], bf[3]);
                }
            }
        }
    };

    // ---- mainloop: 16 chunks; A converted between the two barriers ----
    load_chunk(0, 0);
    #pragma unroll 1
    for (int c = 0; c < 16; c++) {
        CP_WAIT0();
        __syncthreads();                  // chunk c landed; compute(c-1) done everywhere
        convertA(c & 1);
        if (c < 15) load_chunk(c + 1, (c + 1) & 1);
        __syncthreads();                  // A16 conversion visible
        compute(c & 1);
    }
    __syncthreads();

    // ---- expand f16 accumulators to fp32, exponentiate ----
    float acc[2][16][4];
    #pragma unroll
    for (int mi = 0; mi < 2; mi++)
        #pragma unroll
        for (int nf = 0; nf < 16; nf++) {
            float2 lo = __half22float2(*(__half2*)&hacc[mi][nf][0]);
            float2 hi = __half22float2(*(__half2*)&hacc[mi][nf][1]);
            acc[mi][nf][0] = __expf(lo.x * TEMPERATURE);
            acc[mi][nf][1] = __expf(lo.y * TEMPERATURE);
            acc[mi][nf][2] = __expf(hi.x * TEMPERATURE);
            acc[mi][nf][3] = __expf(hi.y * TEMPERATURE);
        }

    // ---- softmax reduction over 4 N-warps ----
    float* red = (float*)S;               // 2 KB scratch in A32 stage 0
    #pragma unroll
    for (int mi = 0; mi < 2; mi++) {
        float sA = 0.0f, sB = 0.0f;
        #pragma unroll
        for (int nf = 0; nf < 16; nf++) {
            sA += acc[mi][nf][0] + acc[mi][nf][1];
            sB += acc[mi][nf][2] + acc[mi][nf][3];
        }
        sA += __shfl_xor_sync(0xffffffffu, sA, 1);
        sA += __shfl_xor_sync(0xffffffffu, sA, 2);
        sB += __shfl_xor_sync(0xffffffffu, sB, 1);
        sB += __shfl_xor_sync(0xffffffffu, sB, 2);
        if ((lid & 3) == 0) {
            int r = wm * 32 + mi * 16 + (lid >> 2);
            red[r * 4 + wn]       = sA;
            red[(r + 8) * 4 + wn] = sB;
        }
    }
    __syncthreads();

    #pragma unroll
    for (int mi = 0; mi < 2; mi++) {
        int rA = wm * 32 + mi * 16 + (lid >> 2), rB = rA + 8;
        float scA = 512.0f / (red[rA * 4] + red[rA * 4 + 1] + red[rA * 4 + 2] + red[rA * 4 + 3]);
        float scB = 512.0f / (red[rB * 4] + red[rB * 4 + 1] + red[rB * 4 + 2] + red[rB * 4 + 3]);
        size_t baseA = (size_t)(bm0 + rA) * 512, baseB = (size_t)(bm0 + rB) * 512;
        #pragma unroll
        for (int nf = 0; nf < 16; nf++) {
            int gc = wn * 128 + nf * 8 + 2 * (lid & 3);
            __half2 pA = __float22half2_rn(make_float2(
                acc[mi][nf][0] * scA - 1.0f, acc[mi][nf][1] * scA - 1.0f));
            __half2 pB = __float22half2_rn(make_float2(
                acc[mi][nf][2] * scB - 1.0f, acc[mi][nf][3] * scB - 1.0f));
            *(uint32_t*)(g_d + baseA + gc) = *(uint32_t*)&pA;
            *(uint32_t*)(g_d + baseB + gc) = *(uint32_t*)&pB;
        }
    }
}

// ============================================================================
// GEMM2 (round-11 exact): out[128 x 512] = vbar + (g_d * VT^T)/512.
//   512 threads = 16 warps (4M x 4N), f16 accumulators, 2-stage cp.async.
// ============================================================================
__global__ void __launch_bounds__(512, 1) gemm2_kernel(float* __restrict__ outp) {
    extern __shared__ char S[];
    const uint32_t sb = smem_u32(S);

    const int tid = threadIdx.x, lid = tid & 31, w = tid >> 5;
    const int wm = w >> 2, wn = w & 3;
    const int bm0 = blockIdx.x * 128;
    const int n_base = (int)blockIdx.y * 512;

    const __half* Asrc = g_d + (size_t)bm0 * 512;
    const __half* Bsrc = g_VT + (size_t)n_base * 512;

    auto load_chunk = [&](int c, int st) {
        const int kc = c * 64;
        const uint32_t ab = sb + st * G2_A_STAGE;
        const uint32_t bb = sb + G2_B_BASE + st * G2_B_STAGE;
        #pragma unroll
        for (int it = 0; it < 2; it++) {
            int u = tid + it * 512, row = u >> 3, seg = u & 7;
            const char* src = (const char*)(Asrc + (size_t)row * 512 + kc + seg * 8);
            CP_ASYNC16(ab + SWZ((uint32_t)(row * 128 + seg * 16)), src);
        }
        #pragma unroll
        for (int it = 0; it < 8; it++) {
            int u = tid + it * 512, row = u >> 3, seg = u & 7;
            const char* src = (const char*)(Bsrc + (size_t)row * 512 + kc + seg * 8);
            CP_ASYNC16(bb + SWZ((uint32_t)(row * 128 + seg * 16)), src);
        }
        CP_COMMIT();
    };

    uint32_t aoff[2], boff[8];
    #pragma unroll
    for (int mi = 0; mi < 2; mi++)
        aoff[mi] = (uint32_t)((wm * 32 + mi * 16 + (lid & 15)) * 128 + (lid >> 4) * 16);
    #pragma unroll
    for (int g = 0; g < 8; g++)
        boff[g] = (uint32_t)((wn * 128 + g * 16 + (lid & 15)) * 128 + (lid >> 4) * 16);

    uint32_t hacc[2][16][2];
    #pragma unroll
    for (int mi = 0; mi < 2; mi++)
        #pragma unroll
        for (int nf = 0; nf < 16; nf++)
            hacc[mi][nf][0] = hacc[mi][nf][1] = 0u;

    auto compute = [&](int st) {
        const uint32_t ab = sb + st * G2_A_STAGE;
        const uint32_t bb = sb + G2_B_BASE + st * G2_B_STAGE;
        #pragma unroll
        for (int ks = 0; ks < 4; ks++) {
            uint32_t a[2][4];
            #pragma unroll
            for (int mi = 0; mi < 2; mi++) LDSM_X4(a[mi], ab + SWZ(aoff[mi] + ks * 32));
            #pragma unroll
            for (int g = 0; g < 8; g++) {
                uint32_t bf[4];
                LDSM_X4(bf, bb + SWZ(boff[g] + ks * 32));
                #pragma unroll
                for (int mi = 0; mi < 2; mi++) {
                    mma16816h(hacc[mi][2 * g],     a[mi], bf[0], bf[2]);
                    mma16816h(hacc[mi][2 * g + 1], a[mi], bf[1], bf[3]);
                }
            }
        }
    };

    load_chunk(0, 0);
    #pragma unroll 1
    for (int c = 0; c < 8; c++) {
        CP_WAIT0();
        __syncthreads();
        if (c + 1 < 8) load_chunk(c + 1, (c + 1) & 1);
        compute(c & 1);
    }

    #pragma unroll
    for (int mi = 0; mi < 2; mi++) {
        int r = wm * 32 + mi * 16 + (lid >> 2);
        size_t rowA = (size_t)(bm0 + r) * 1024, rowB = (size_t)(bm0 + r + 8) * 1024;
        #pragma unroll
        for (int nf = 0; nf < 16; nf++) {
            float2 lo = __half22float2(*(__half2*)&hacc[mi][nf][0]);
            float2 hi = __half22float2(*(__half2*)&hacc[mi][nf][1]);
            int gc = n_base + wn * 128 + nf * 8 + 2 * (lid & 3);
            float2 vb = *(const float2*)(g_vbar + gc);
            float2 o0 = make_float2(fmaf(lo.x, (1.0f / 512.0f), vb.x),
                                    fmaf(lo.y, (1.0f / 512.0f), vb.y));
            float2 o1 = make_float2(fmaf(hi.x, (1.0f / 512.0f), vb.x),
                                    fmaf(hi.y, (1.0f / 512.0f), vb.y));
            *(float2*)(outp + rowA + gc) = o0;
            *(float2*)(outp + rowB + gc) = o1;
        }
    }
}

// ============================================================================
extern "C" void kernel_launch(void* const* d_in, const int* in_sizes, int n_in,
                              void* d_out, int out_size) {
    (void)in_sizes; (void)n_in; (void)out_size;
    const float* x  = (const float*)d_in[0];
    const float* kr = (const float*)d_in[1];
    const float* ki = (const float*)d_in[2];
    const float* vr = (const float*)d_in[3];
    const float* vi = (const float*)d_in[4];
    float* out = (float*)d_out;

    cudaFuncSetAttribute(gemm1_kernel, cudaFuncAttributeMaxDynamicSharedMemorySize, G1_SMEM);
    cudaFuncSetAttribute(gemm2_kernel, cudaFuncAttributeMaxDynamicSharedMemorySize, G2_SMEM);

    prep_kernel<<<1536, 256>>>(kr, ki, vr, vi);
    gemm1_kernel<<<256, 512, G1_SMEM>>>(x);
    gemm2_kernel<<<dim3(256, 2), 512, G2_SMEM>>>(out);
}